// round 15
// baseline (speedup 1.0000x reference)
#include <cuda_runtime.h>
#include <cuda_fp16.h>
#include <cuda_bf16.h>

#define N_NODES   100000
#define N_EDGES   3200000
#define IN_DIM    128
#define HID       64
#define OUT_DIM   128
#define N_GRAPHS  8
#define WFIX      1048576.0f          // 2^20 fixed-point scale for weights

// ---------------- scratch (static __device__, no allocs) ----------------
__device__ unsigned long long g_pk[N_NODES];            // {count:24 | wsum.20fix:40}
__device__ float g_dinv[N_NODES];
__device__ float g_scale[N_NODES];                      // per-row dequant scale
__device__ int   g_cnt_e[N_NODES];
__device__ int   g_rowptr[N_NODES];                     // per-row base (non-ordered)
__device__ int   g_total;
__device__ int   g_epos[N_EDGES];                       // within-row position per edge
__device__ __align__(16) int2  g_edge[N_EDGES];         // {src, (dinv[s]*w) bits}
__device__ __align__(16) unsigned char g_bufQ[N_NODES * HID];  // int8 features
__device__ __align__(16) float g_bufA[N_NODES * HID];
__device__ __align__(16) float g_bufB[N_NODES * HID];
__device__ float g_pool[N_GRAPHS * HID];
__device__ float g_cnt[N_GRAPHS];

// ---------------- init: packed (count=0, wsum=1.0 self loop); totals ----------------
__global__ void k_init0(int n) {
    int i = blockIdx.x * blockDim.x + threadIdx.x;
    if (i < n) g_pk[i] = (unsigned long long)(1u << 20);   // weight 1.0 fixed
    if (i < N_GRAPHS * HID) g_pool[i] = 0.0f;
    if (i < N_GRAPHS) g_cnt[i] = 0.0f;
    if (i == 0) g_total = 0;
}

// quantize 8 floats to int8 with given inverse scale; pack to uint2
__device__ __forceinline__ uint2 quant8(const float* a, float inv) {
    unsigned int q[8];
#pragma unroll
    for (int j = 0; j < 8; j++)
        q[j] = (unsigned int)__float2int_rn(a[j] * inv) & 0xffu;
    uint2 r;
    r.x = q[0] | (q[1] << 8) | (q[2] << 16) | (q[3] << 24);
    r.y = q[4] | (q[5] << 8) | (q[6] << 16) | (q[7] << 24);
    return r;
}

// unpack 8 int8 from uint2 to floats
__device__ __forceinline__ void unpack8(uint2 u, float* o) {
    o[0] = (float)(int)(char)(u.x);
    o[1] = (float)(int)(char)(u.x >> 8);
    o[2] = (float)(int)(char)(u.x >> 16);
    o[3] = (float)(int)(char)(u.x >> 24);
    o[4] = (float)(int)(char)(u.y);
    o[5] = (float)(int)(char)(u.y >> 8);
    o[6] = (float)(int)(char)(u.y >> 16);
    o[7] = (float)(int)(char)(u.y >> 24);
}

// gemm epilogue: per-row max across the 8 owning lanes, quantize, store row+scale
__device__ __forceinline__ void store_q_rows(unsigned char* __restrict__ Y,
                                             float acc[4][8], int row0, int r0,
                                             int c0, int tx, int n) {
#pragma unroll
    for (int i = 0; i < 4; i++) {
        float m = 0.0f;
#pragma unroll
        for (int j = 0; j < 8; j++) m = fmaxf(m, fabsf(acc[i][j]));
#pragma unroll
        for (int off = 1; off < 8; off <<= 1)
            m = fmaxf(m, __shfl_xor_sync(0xffffffffu, m, off));
        int row = row0 + r0 + i;
        if (row < n) {
            float inv = (m > 0.0f) ? (127.0f / m) : 0.0f;
            *(uint2*)(Y + row * 64 + c0) = quant8(acc[i], inv);
            if (tx == 0) g_scale[row] = m * (1.0f / 127.0f);
        }
    }
}

// ---------------- FUSED: gemm1 (blocks < GB) || edge count (blocks >= GB) --------
// gemm1: bufQ[n x 64] = x[n x 128] @ W1 (int8 + row scale out).
// count: 4 edges/thread, ONE packed 64-bit atomic per edge.
__global__ void k_gemm1_count(const float* __restrict__ X, const float* __restrict__ W,
                              unsigned char* __restrict__ Y,
                              const int* __restrict__ dst, const float* __restrict__ w,
                              int n, int E, int GB) {
    __shared__ float Xs[128 * 33];
    __shared__ float Ws[32 * 64];
    int t = threadIdx.x;

    if (blockIdx.x >= GB) {
        // -------- count role: 4 edges/thread --------
        int i0 = ((blockIdx.x - GB) * 256 + t) * 4;
        if (i0 >= E) return;
        if (i0 + 3 < E) {
            int4   d4 = *(const int4*)(dst + i0);
            float4 w4 = *(const float4*)(w + i0);
            unsigned long long i0v = (1ULL << 40) | (unsigned long long)__float2uint_rn(w4.x * WFIX);
            unsigned long long i1v = (1ULL << 40) | (unsigned long long)__float2uint_rn(w4.y * WFIX);
            unsigned long long i2v = (1ULL << 40) | (unsigned long long)__float2uint_rn(w4.z * WFIX);
            unsigned long long i3v = (1ULL << 40) | (unsigned long long)__float2uint_rn(w4.w * WFIX);
            unsigned long long o0 = atomicAdd(&g_pk[d4.x], i0v);
            unsigned long long o1 = atomicAdd(&g_pk[d4.y], i1v);
            unsigned long long o2 = atomicAdd(&g_pk[d4.z], i2v);
            unsigned long long o3 = atomicAdd(&g_pk[d4.w], i3v);
            *(int4*)(g_epos + i0) = make_int4((int)(o0 >> 40), (int)(o1 >> 40),
                                              (int)(o2 >> 40), (int)(o3 >> 40));
        } else {
            for (int e = i0; e < E; e++) {
                int d = dst[e];
                unsigned long long inc = (1ULL << 40) | (unsigned long long)__float2uint_rn(w[e] * WFIX);
                unsigned long long old = atomicAdd(&g_pk[d], inc);
                g_epos[e] = (int)(old >> 40);
            }
        }
        return;
    }

    // -------- gemm role (K = IN_DIM = 128) --------
    int row0 = blockIdx.x * 128;
    int tx = t & 7;
    int ty = t >> 3;
    int c0 = tx * 8;
    int r0 = ty * 4;

    float acc[4][8];
#pragma unroll
    for (int i = 0; i < 4; i++)
#pragma unroll
        for (int j = 0; j < 8; j++) acc[i][j] = 0.0f;

    for (int kc = 0; kc < IN_DIM; kc += 32) {
#pragma unroll
        for (int i = t; i < 32 * 64; i += 256) Ws[i] = W[(kc + (i >> 6)) * 64 + (i & 63)];
#pragma unroll
        for (int i = t; i < 128 * 32; i += 256) {
            int r = i >> 5, k = i & 31;
            int gr = row0 + r;
            Xs[r * 33 + k] = (gr < n) ? X[gr * IN_DIM + kc + k] : 0.0f;
        }
        __syncthreads();

#pragma unroll
        for (int k = 0; k < 32; k++) {
            float xv[4];
#pragma unroll
            for (int i = 0; i < 4; i++) xv[i] = Xs[(r0 + i) * 33 + k];
            float4 w0 = *(const float4*)&Ws[k * 64 + c0];
            float4 w1 = *(const float4*)&Ws[k * 64 + c0 + 4];
            float wv[8] = {w0.x, w0.y, w0.z, w0.w, w1.x, w1.y, w1.z, w1.w};
#pragma unroll
            for (int i = 0; i < 4; i++)
#pragma unroll
                for (int j = 0; j < 8; j++) acc[i][j] += xv[i] * wv[j];
        }
        __syncthreads();
    }

    store_q_rows(Y, acc, row0, r0, c0, tx, n);
}

// ---------------- fused scan: unpack pk -> dinv/cnt; rowptr via atomic base ----------
__global__ void k_scan(int n) {
    __shared__ int sh[256];
    __shared__ int base_sh;
    int t = threadIdx.x;
    int i0 = blockIdx.x * 1024 + t * 4;
    int v[4]; int s = 0;
#pragma unroll
    for (int j = 0; j < 4; j++) {
        int i = i0 + j;
        int c = 0;
        if (i < n) {
            unsigned long long pk = g_pk[i];
            c = (int)(pk >> 40);
            float deg = (float)(pk & ((1ULL << 40) - 1)) * (1.0f / WFIX);
            g_dinv[i] = rsqrtf(deg);
            g_cnt_e[i] = c;
        }
        v[j] = c;
        s += c;
    }
    sh[t] = s; __syncthreads();
    for (int off = 1; off < 256; off <<= 1) {
        int x = (t >= off) ? sh[t - off] : 0;
        __syncthreads();
        sh[t] += x;
        __syncthreads();
    }
    if (t == 255) base_sh = atomicAdd(&g_total, sh[255]);
    __syncthreads();
    int run = base_sh + sh[t] - s;
#pragma unroll
    for (int j = 0; j < 4; j++) {
        int i = i0 + j;
        if (i < n) g_rowptr[i] = run;
        run += v[j];
    }
}

// ---------------- fill CSR (by dst): 4 edges/thread, normS = dinv[s]*w ----------
__global__ void k_fill(const int* __restrict__ src, const int* __restrict__ dst,
                       const float* __restrict__ w, int E) {
    int i0 = (blockIdx.x * blockDim.x + threadIdx.x) * 4;
    if (i0 >= E) return;
    if (i0 + 3 < E) {
        int4   s4 = *(const int4*)(src + i0);
        int4   d4 = *(const int4*)(dst + i0);
        int4   e4 = *(const int4*)(g_epos + i0);
        float4 w4 = *(const float4*)(w + i0);
        float ds0 = g_dinv[s4.x], ds1 = g_dinv[s4.y], ds2 = g_dinv[s4.z], ds3 = g_dinv[s4.w];
        int   r0 = g_rowptr[d4.x], r1 = g_rowptr[d4.y], r2 = g_rowptr[d4.z], r3 = g_rowptr[d4.w];
        g_edge[r0 + e4.x] = make_int2(s4.x, __float_as_int(ds0 * w4.x));
        g_edge[r1 + e4.y] = make_int2(s4.y, __float_as_int(ds1 * w4.y));
        g_edge[r2 + e4.z] = make_int2(s4.z, __float_as_int(ds2 * w4.z));
        g_edge[r3 + e4.w] = make_int2(s4.w, __float_as_int(ds3 * w4.w));
    } else {
        for (int e = i0; e < E; e++) {
            int s = src[e], d = dst[e];
            int pos = g_rowptr[d] + g_epos[e];
            g_edge[pos] = make_int2(s, __float_as_int(g_dinv[s] * w[e]));
        }
    }
}

// ---------------- register-tiled GEMM (conv2): relu(X+b) in, int8+scale out --------
__global__ void k_gemm2(const float* __restrict__ X, const float* __restrict__ W,
                        const float* __restrict__ bias, unsigned char* __restrict__ Y, int n) {
    __shared__ float Xs[128 * 33];
    __shared__ float Ws[32 * 64];

    int t = threadIdx.x;
    int row0 = blockIdx.x * 128;
    int tx = t & 7;
    int ty = t >> 3;
    int c0 = tx * 8;
    int r0 = ty * 4;

    float acc[4][8];
#pragma unroll
    for (int i = 0; i < 4; i++)
#pragma unroll
        for (int j = 0; j < 8; j++) acc[i][j] = 0.0f;

    for (int kc = 0; kc < HID; kc += 32) {
#pragma unroll
        for (int i = t; i < 32 * 64; i += 256) Ws[i] = W[(kc + (i >> 6)) * 64 + (i & 63)];
#pragma unroll
        for (int i = t; i < 128 * 32; i += 256) {
            int r = i >> 5, k = i & 31;
            int gr = row0 + r;
            float v = (gr < n) ? X[gr * HID + kc + k] : 0.0f;
            v = fmaxf(v + __ldg(&bias[kc + k]), 0.0f);
            Xs[r * 33 + k] = v;
        }
        __syncthreads();

#pragma unroll
        for (int k = 0; k < 32; k++) {
            float xv[4];
#pragma unroll
            for (int i = 0; i < 4; i++) xv[i] = Xs[(r0 + i) * 33 + k];
            float4 w0 = *(const float4*)&Ws[k * 64 + c0];
            float4 w1 = *(const float4*)&Ws[k * 64 + c0 + 4];
            float wv[8] = {w0.x, w0.y, w0.z, w0.w, w1.x, w1.y, w1.z, w1.w};
#pragma unroll
            for (int i = 0; i < 4; i++)
#pragma unroll
                for (int j = 0; j < 8; j++) acc[i][j] += xv[i] * wv[j];
        }
        __syncthreads();
    }

    store_q_rows(Y, acc, row0, r0, c0, tx, n);
}

// ---------------- gather conv, int8 H: OUT[d] = dv*(dv*sc_d*Q[d] + sum normS*sc_s*Q[src]) --
// warp per node: 8 feature lanes (8 int8 = 8B each) x 4 edge slots; end = rowptr + cnt.
__global__ void k_gather_q(const unsigned char* __restrict__ H, float* __restrict__ OUT, int n) {
    int t = threadIdx.x;
    int fl   = t & 7;             // feature lane: bytes [fl*8, fl*8+8)
    int slot = (t >> 3) & 3;      // edge slot 0..3
    int node = blockIdx.x * 8 + (t >> 5);
    if (node >= n) return;

    const uint2* Hp = (const uint2*)H;   // 8 uint2 per 64B row

    float f[8];
#pragma unroll
    for (int j = 0; j < 8; j++) f[j] = 0.0f;

    float dv = g_dinv[node];
    if (slot == 0) {
        float sc = dv * g_scale[node];
        uint2 u = Hp[node * 8 + fl];
        float q[8]; unpack8(u, q);
#pragma unroll
        for (int j = 0; j < 8; j++) f[j] = sc * q[j];
    }

    int beg = g_rowptr[node];
    int end = beg + g_cnt_e[node];
    int e = beg + slot;
    for (; e + 4 < end; e += 8) {
        int2 e0 = g_edge[e];
        int2 e1 = g_edge[e + 4];
        uint2 u0 = Hp[e0.x * 8 + fl];
        uint2 u1 = Hp[e1.x * 8 + fl];
        float n0 = __int_as_float(e0.y) * g_scale[e0.x];
        float n1 = __int_as_float(e1.y) * g_scale[e1.x];
        float q0[8], q1[8];
        unpack8(u0, q0);
        unpack8(u1, q1);
#pragma unroll
        for (int j = 0; j < 8; j++)
            f[j] += n0 * q0[j] + n1 * q1[j];
    }
    for (; e < end; e += 4) {
        int2 e0 = g_edge[e];
        uint2 u0 = Hp[e0.x * 8 + fl];
        float n0 = __int_as_float(e0.y) * g_scale[e0.x];
        float q0[8];
        unpack8(u0, q0);
#pragma unroll
        for (int j = 0; j < 8; j++)
            f[j] += n0 * q0[j];
    }

    // reduce across the 4 edge slots (xor 8, xor 16)
#pragma unroll
    for (int off = 8; off < 32; off <<= 1)
#pragma unroll
        for (int j = 0; j < 8; j++)
            f[j] += __shfl_xor_sync(0xffffffffu, f[j], off);

    if (slot == 0) {
        float4 o0 = {dv * f[0], dv * f[1], dv * f[2], dv * f[3]};
        float4 o1 = {dv * f[4], dv * f[5], dv * f[6], dv * f[7]};
        *(float4*)&OUT[node * 64 + fl * 8]     = o0;
        *(float4*)&OUT[node * 64 + fl * 8 + 4] = o1;
    }
}

// ---------------- pool: two-stage segment sum over batch ids ----------------
#define POOL_NB 512
__global__ void k_pool(const float* __restrict__ AGG,
                       const int* __restrict__ batch, int n) {
    __shared__ float acc[N_GRAPHS][HID];
    __shared__ float scnt[N_GRAPHS];
    for (int i = threadIdx.x; i < N_GRAPHS * HID; i += 256)
        acc[i / HID][i % HID] = 0.f;
    if (threadIdx.x < N_GRAPHS) scnt[threadIdx.x] = 0.f;
    __syncthreads();

    int c  = threadIdx.x & 63;
    int nl = threadIdx.x >> 6;
    int base = blockIdx.x * POOL_NB;
    int lim = min(base + POOL_NB, n);
    for (int i = base + nl; i < lim; i += 4) {
        int b = batch[i];
        atomicAdd(&acc[b][c], AGG[i * 64 + c]);
        if (c == 0) atomicAdd(&scnt[b], 1.0f);
    }
    __syncthreads();
    for (int i = threadIdx.x; i < N_GRAPHS * HID; i += 256)
        atomicAdd(&g_pool[i], acc[i / HID][i % HID]);
    if (threadIdx.x < N_GRAPHS) atomicAdd(&g_cnt[threadIdx.x], scnt[threadIdx.x]);
}

// ---------------- final: out[g][o] = (pool[g]/cnt[g] + b2) @ Wfc + bfc ----------------
__global__ void k_final(const float* __restrict__ b2, const float* __restrict__ Wfc,
                        const float* __restrict__ bfc, float* __restrict__ out) {
    __shared__ float P[N_GRAPHS][HID];
    for (int i = threadIdx.x; i < N_GRAPHS * HID; i += 128) {
        int g = i / HID, c = i % HID;
        float cnt = fmaxf(g_cnt[g], 1.0f);
        P[g][c] = g_pool[i] / cnt + b2[c];
    }
    __syncthreads();
    int o = threadIdx.x;   // 128 threads
    for (int g = 0; g < N_GRAPHS; g++) {
        float s = bfc[o];
#pragma unroll
        for (int c = 0; c < HID; c++)
            s += P[g][c] * Wfc[c * OUT_DIM + o];
        out[g * OUT_DIM + o] = s;
    }
}

// ---------------- launcher ----------------
extern "C" void kernel_launch(void* const* d_in, const int* in_sizes, int n_in,
                              void* d_out, int out_size) {
    const float* x   = (const float*)d_in[0];
    const int*   ei  = (const int*)d_in[1];     // int64 inputs arrive as int32
    const float* ew  = (const float*)d_in[2];
    const int*   bat = (const int*)d_in[3];
    const float* W1  = (const float*)d_in[4];
    const float* b1  = (const float*)d_in[5];
    const float* W2  = (const float*)d_in[6];
    const float* b2  = (const float*)d_in[7];
    const float* Wfc = (const float*)d_in[8];
    const float* bfc = (const float*)d_in[9];
    float* out = (float*)d_out;

    int n = in_sizes[0] / IN_DIM;      // 100000
    int E = in_sizes[2];               // 3200000
    const int* src = ei;
    const int* dst = ei + E;

    float *bufA, *bufB;
    unsigned char* bufQ;
    cudaGetSymbolAddress((void**)&bufA, g_bufA);
    cudaGetSymbolAddress((void**)&bufB, g_bufB);
    cudaGetSymbolAddress((void**)&bufQ, g_bufQ);

    int gE4 = (E / 4 + 255) / 256;                // 3125 count/fill blocks
    int gN  = (n + 255) / 256;
    int GB  = (n + 127) / 128;                    // 782 gemm blocks
    int nsb = (n + 1023) / 1024;                  // 98 scan blocks

    // ---- init; fused gemm1 || count; fused scan; fill ----
    k_init0<<<gN, 256>>>(n);
    k_gemm1_count<<<GB + gE4, 256>>>(x, W1, bufQ, dst, ew, n, E, GB);
    k_scan<<<nsb, 256>>>(n);
    k_fill<<<gE4, 256>>>(src, dst, ew, E);

    // ---- conv1 gather: agg1 -> bufB (fp32) ----
    k_gather_q<<<(n + 7) / 8, 256>>>(bufQ, bufB, n);

    // ---- conv2: h2 = relu(agg1 + b1) @ W2 -> bufQ (int8+scale) ; agg2 -> bufA ----
    k_gemm2<<<GB, 256>>>(bufB, W2, b1, bufQ, n);
    k_gather_q<<<(n + 7) / 8, 256>>>(bufQ, bufA, n);

    // ---- pool (b2 folded into final) + fc ----
    k_pool<<<(n + POOL_NB - 1) / POOL_NB, 256>>>(bufA, bat, n);
    k_final<<<1, 128>>>(b2, Wfc, bfc, out);
}

// round 16
// speedup vs baseline: 1.0581x; 1.0581x over previous
#include <cuda_runtime.h>
#include <cuda_fp16.h>
#include <cuda_bf16.h>

#define N_NODES   100000
#define N_EDGES   3200000
#define IN_DIM    128
#define HID       64
#define OUT_DIM   128
#define N_GRAPHS  8
#define WFIX      1048576.0f          // 2^20 fixed-point scale for weights
#define GP_BLOCKS 1184                // one full wave (148 SMs x 8 blocks)

// ---------------- scratch (static __device__, no allocs) ----------------
__device__ unsigned long long g_pk[N_NODES];            // {count:24 | wsum.20fix:40}
__device__ float g_dinv[N_NODES];
__device__ int   g_cnt_e[N_NODES];
__device__ int   g_rowptr[N_NODES];                     // per-row base (non-ordered)
__device__ int   g_total;
__device__ int   g_epos[N_EDGES];                       // within-row position per edge
__device__ __align__(16) int2  g_edge[N_EDGES];         // {src, (dinv[s]*w) bits}
__device__ __align__(16) __half g_bufH[N_NODES * HID];  // fp16 features for gathers
__device__ __align__(16) float g_bufB[N_NODES * HID];
__device__ float g_pool[N_GRAPHS * HID];
__device__ float g_cnt[N_GRAPHS];

// ---------------- init: packed (count=0, wsum=1.0 self loop); totals ----------------
__global__ void k_init0(int n) {
    int i = blockIdx.x * blockDim.x + threadIdx.x;
    if (i < n) g_pk[i] = (unsigned long long)(1u << 20);   // weight 1.0 fixed
    if (i < N_GRAPHS * HID) g_pool[i] = 0.0f;
    if (i < N_GRAPHS) g_cnt[i] = 0.0f;
    if (i == 0) g_total = 0;
}

// ---------------- count: 4 edges/thread, ONE packed 64-bit atomic per edge ---------
__global__ void k_count(const int* __restrict__ dst,
                        const float* __restrict__ w, int E) {
    int i0 = (blockIdx.x * blockDim.x + threadIdx.x) * 4;
    if (i0 >= E) return;
    if (i0 + 3 < E) {
        int4   d4 = *(const int4*)(dst + i0);
        float4 w4 = *(const float4*)(w + i0);
        unsigned long long i0v = (1ULL << 40) | (unsigned long long)__float2uint_rn(w4.x * WFIX);
        unsigned long long i1v = (1ULL << 40) | (unsigned long long)__float2uint_rn(w4.y * WFIX);
        unsigned long long i2v = (1ULL << 40) | (unsigned long long)__float2uint_rn(w4.z * WFIX);
        unsigned long long i3v = (1ULL << 40) | (unsigned long long)__float2uint_rn(w4.w * WFIX);
        unsigned long long o0 = atomicAdd(&g_pk[d4.x], i0v);
        unsigned long long o1 = atomicAdd(&g_pk[d4.y], i1v);
        unsigned long long o2 = atomicAdd(&g_pk[d4.z], i2v);
        unsigned long long o3 = atomicAdd(&g_pk[d4.w], i3v);
        *(int4*)(g_epos + i0) = make_int4((int)(o0 >> 40), (int)(o1 >> 40),
                                          (int)(o2 >> 40), (int)(o3 >> 40));
    } else {
        for (int e = i0; e < E; e++) {
            int d = dst[e];
            unsigned long long inc = (1ULL << 40) | (unsigned long long)__float2uint_rn(w[e] * WFIX);
            unsigned long long old = atomicAdd(&g_pk[d], inc);
            g_epos[e] = (int)(old >> 40);
        }
    }
}

// ---------------- fused scan: unpack pk -> dinv/cnt; rowptr via atomic base ----------
__global__ void k_scan(int n) {
    __shared__ int sh[256];
    __shared__ int base_sh;
    int t = threadIdx.x;
    int i0 = blockIdx.x * 1024 + t * 4;
    int v[4]; int s = 0;
#pragma unroll
    for (int j = 0; j < 4; j++) {
        int i = i0 + j;
        int c = 0;
        if (i < n) {
            unsigned long long pk = g_pk[i];
            c = (int)(pk >> 40);
            float deg = (float)(pk & ((1ULL << 40) - 1)) * (1.0f / WFIX);
            g_dinv[i] = rsqrtf(deg);
            g_cnt_e[i] = c;
        }
        v[j] = c;
        s += c;
    }
    sh[t] = s; __syncthreads();
    for (int off = 1; off < 256; off <<= 1) {
        int x = (t >= off) ? sh[t - off] : 0;
        __syncthreads();
        sh[t] += x;
        __syncthreads();
    }
    if (t == 255) base_sh = atomicAdd(&g_total, sh[255]);
    __syncthreads();
    int run = base_sh + sh[t] - s;
#pragma unroll
    for (int j = 0; j < 4; j++) {
        int i = i0 + j;
        if (i < n) g_rowptr[i] = run;
        run += v[j];
    }
}

// ---------------- FUSED: gemm1 (blocks < GB) || CSR fill (blocks >= GB) ----------
// gemm1: bufH[n x 64] = x[n x 128] @ W1 (fp16 out) — depends only on x, W1.
// fill:  4 edges/thread, normS = dinv[s]*w — depends on count+scan (done).
__global__ void k_gemm1_fill(const float* __restrict__ X, const float* __restrict__ W,
                             __half* __restrict__ Y,
                             const int* __restrict__ src, const int* __restrict__ dst,
                             const float* __restrict__ w,
                             int n, int E, int GB) {
    __shared__ float Xs[128 * 33];
    __shared__ float Ws[32 * 64];
    int t = threadIdx.x;

    if (blockIdx.x >= GB) {
        // -------- fill role: 4 edges/thread --------
        int i0 = ((blockIdx.x - GB) * 256 + t) * 4;
        if (i0 >= E) return;
        if (i0 + 3 < E) {
            int4   s4 = *(const int4*)(src + i0);
            int4   d4 = *(const int4*)(dst + i0);
            int4   e4 = *(const int4*)(g_epos + i0);
            float4 w4 = *(const float4*)(w + i0);
            float ds0 = g_dinv[s4.x], ds1 = g_dinv[s4.y], ds2 = g_dinv[s4.z], ds3 = g_dinv[s4.w];
            int   r0 = g_rowptr[d4.x], r1 = g_rowptr[d4.y], r2 = g_rowptr[d4.z], r3 = g_rowptr[d4.w];
            g_edge[r0 + e4.x] = make_int2(s4.x, __float_as_int(ds0 * w4.x));
            g_edge[r1 + e4.y] = make_int2(s4.y, __float_as_int(ds1 * w4.y));
            g_edge[r2 + e4.z] = make_int2(s4.z, __float_as_int(ds2 * w4.z));
            g_edge[r3 + e4.w] = make_int2(s4.w, __float_as_int(ds3 * w4.w));
        } else {
            for (int e = i0; e < E; e++) {
                int s = src[e], d = dst[e];
                int pos = g_rowptr[d] + g_epos[e];
                g_edge[pos] = make_int2(s, __float_as_int(g_dinv[s] * w[e]));
            }
        }
        return;
    }

    // -------- gemm role (K = IN_DIM = 128) --------
    int row0 = blockIdx.x * 128;
    int tx = t & 7;
    int ty = t >> 3;
    int c0 = tx * 8;
    int r0 = ty * 4;

    float acc[4][8];
#pragma unroll
    for (int i = 0; i < 4; i++)
#pragma unroll
        for (int j = 0; j < 8; j++) acc[i][j] = 0.0f;

    for (int kc = 0; kc < IN_DIM; kc += 32) {
#pragma unroll
        for (int i = t; i < 32 * 64; i += 256) Ws[i] = W[(kc + (i >> 6)) * 64 + (i & 63)];
#pragma unroll
        for (int i = t; i < 128 * 32; i += 256) {
            int r = i >> 5, k = i & 31;
            int gr = row0 + r;
            Xs[r * 33 + k] = (gr < n) ? X[gr * IN_DIM + kc + k] : 0.0f;
        }
        __syncthreads();

#pragma unroll
        for (int k = 0; k < 32; k++) {
            float xv[4];
#pragma unroll
            for (int i = 0; i < 4; i++) xv[i] = Xs[(r0 + i) * 33 + k];
            float4 w0 = *(const float4*)&Ws[k * 64 + c0];
            float4 w1 = *(const float4*)&Ws[k * 64 + c0 + 4];
            float wv[8] = {w0.x, w0.y, w0.z, w0.w, w1.x, w1.y, w1.z, w1.w};
#pragma unroll
            for (int i = 0; i < 4; i++)
#pragma unroll
                for (int j = 0; j < 8; j++) acc[i][j] += xv[i] * wv[j];
        }
        __syncthreads();
    }

#pragma unroll
    for (int i = 0; i < 4; i++) {
        int row = row0 + r0 + i;
        if (row < n) {
            __half2 h[4];
#pragma unroll
            for (int j = 0; j < 4; j++)
                h[j] = __floats2half2_rn(acc[i][2 * j], acc[i][2 * j + 1]);
            *(uint4*)(Y + row * 64 + c0) = *(uint4*)h;
        }
    }
}

// ---------------- gather body (fp16): returns dv and f[8] for one node ----------
__device__ __forceinline__ float gather_node(const uint4* __restrict__ Hp,
                                             int node, int fl, int slot, float* f) {
#pragma unroll
    for (int j = 0; j < 8; j++) f[j] = 0.0f;
    float dv = g_dinv[node];
    if (slot == 0) {
        uint4 u = Hp[node * 8 + fl];
        const __half2* hp = (const __half2*)&u;
#pragma unroll
        for (int j = 0; j < 4; j++) {
            float2 v = __half22float2(hp[j]);
            f[2 * j]     = dv * v.x;
            f[2 * j + 1] = dv * v.y;
        }
    }
    int beg = g_rowptr[node];
    int end = beg + g_cnt_e[node];
    int e = beg + slot;
    for (; e + 4 < end; e += 8) {
        int2 e0 = g_edge[e];
        int2 e1 = g_edge[e + 4];
        uint4 u0 = Hp[e0.x * 8 + fl];
        uint4 u1 = Hp[e1.x * 8 + fl];
        float n0 = __int_as_float(e0.y);
        float n1 = __int_as_float(e1.y);
        const __half2* h0 = (const __half2*)&u0;
        const __half2* h1 = (const __half2*)&u1;
#pragma unroll
        for (int j = 0; j < 4; j++) {
            float2 v0 = __half22float2(h0[j]);
            float2 v1 = __half22float2(h1[j]);
            f[2 * j]     += n0 * v0.x + n1 * v1.x;
            f[2 * j + 1] += n0 * v0.y + n1 * v1.y;
        }
    }
    for (; e < end; e += 4) {
        int2 e0 = g_edge[e];
        uint4 u0 = Hp[e0.x * 8 + fl];
        float n0 = __int_as_float(e0.y);
        const __half2* h0 = (const __half2*)&u0;
#pragma unroll
        for (int j = 0; j < 4; j++) {
            float2 v0 = __half22float2(h0[j]);
            f[2 * j]     += n0 * v0.x;
            f[2 * j + 1] += n0 * v0.y;
        }
    }
    // reduce across the 4 edge slots (xor 8, xor 16)
#pragma unroll
    for (int off = 8; off < 32; off <<= 1)
#pragma unroll
        for (int j = 0; j < 8; j++)
            f[j] += __shfl_xor_sync(0xffffffffu, f[j], off);
    return dv;
}

// ---------------- conv1 gather: OUT fp32 ----------------
__global__ void k_gather_h(const __half* __restrict__ H, float* __restrict__ OUT, int n) {
    int t = threadIdx.x;
    int fl = t & 7, slot = (t >> 3) & 3;
    int node = blockIdx.x * 8 + (t >> 5);
    if (node >= n) return;
    float f[8];
    float dv = gather_node((const uint4*)H, node, fl, slot, f);
    if (slot == 0) {
        float4 o0 = {dv * f[0], dv * f[1], dv * f[2], dv * f[3]};
        float4 o1 = {dv * f[4], dv * f[5], dv * f[6], dv * f[7]};
        *(float4*)&OUT[node * 64 + fl * 8]     = o0;
        *(float4*)&OUT[node * 64 + fl * 8 + 4] = o1;
    }
}

// ---------------- register-tiled GEMM (conv2): relu(X+b) in, fp16 out ----------------
__global__ void k_gemm2(const float* __restrict__ X, const float* __restrict__ W,
                        const float* __restrict__ bias, __half* __restrict__ Y, int n) {
    __shared__ float Xs[128 * 33];
    __shared__ float Ws[32 * 64];

    int t = threadIdx.x;
    int row0 = blockIdx.x * 128;
    int tx = t & 7;
    int ty = t >> 3;
    int c0 = tx * 8;
    int r0 = ty * 4;

    float acc[4][8];
#pragma unroll
    for (int i = 0; i < 4; i++)
#pragma unroll
        for (int j = 0; j < 8; j++) acc[i][j] = 0.0f;

    for (int kc = 0; kc < HID; kc += 32) {
#pragma unroll
        for (int i = t; i < 32 * 64; i += 256) Ws[i] = W[(kc + (i >> 6)) * 64 + (i & 63)];
#pragma unroll
        for (int i = t; i < 128 * 32; i += 256) {
            int r = i >> 5, k = i & 31;
            int gr = row0 + r;
            float v = (gr < n) ? X[gr * HID + kc + k] : 0.0f;
            v = fmaxf(v + __ldg(&bias[kc + k]), 0.0f);
            Xs[r * 33 + k] = v;
        }
        __syncthreads();

#pragma unroll
        for (int k = 0; k < 32; k++) {
            float xv[4];
#pragma unroll
            for (int i = 0; i < 4; i++) xv[i] = Xs[(r0 + i) * 33 + k];
            float4 w0 = *(const float4*)&Ws[k * 64 + c0];
            float4 w1 = *(const float4*)&Ws[k * 64 + c0 + 4];
            float wv[8] = {w0.x, w0.y, w0.z, w0.w, w1.x, w1.y, w1.z, w1.w};
#pragma unroll
            for (int i = 0; i < 4; i++)
#pragma unroll
                for (int j = 0; j < 8; j++) acc[i][j] += xv[i] * wv[j];
        }
        __syncthreads();
    }

#pragma unroll
    for (int i = 0; i < 4; i++) {
        int row = row0 + r0 + i;
        if (row < n) {
            __half2 h[4];
#pragma unroll
            for (int j = 0; j < 4; j++)
                h[j] = __floats2half2_rn(acc[i][2 * j], acc[i][2 * j + 1]);
            *(uint4*)(Y + row * 64 + c0) = *(uint4*)h;
        }
    }
}

// ---------------- FUSED conv2 gather + pool: grid-stride, smem accumulators ------
__global__ void k_gather_pool(const __half* __restrict__ H,
                              const int* __restrict__ batch, int n) {
    __shared__ float acc[N_GRAPHS][HID];
    __shared__ float scnt[N_GRAPHS];
    int t = threadIdx.x;
    for (int i = t; i < N_GRAPHS * HID; i += 256) acc[i >> 6][i & 63] = 0.0f;
    if (t < N_GRAPHS) scnt[t] = 0.0f;
    __syncthreads();

    int fl = t & 7, slot = (t >> 3) & 3, wrp = t >> 5;
    const uint4* Hp = (const uint4*)H;
    int ngroups = (n + 7) / 8;
    for (int g = blockIdx.x; g < ngroups; g += gridDim.x) {
        int node = g * 8 + wrp;
        if (node < n) {
            float f[8];
            float dv = gather_node(Hp, node, fl, slot, f);
            if (slot == 0) {
                int b = batch[node];
#pragma unroll
                for (int j = 0; j < 8; j++)
                    atomicAdd(&acc[b][fl * 8 + j], dv * f[j]);
                if (fl == 0) atomicAdd(&scnt[b], 1.0f);
            }
        }
    }
    __syncthreads();
    for (int i = t; i < N_GRAPHS * HID; i += 256)
        atomicAdd(&g_pool[i], acc[i >> 6][i & 63]);
    if (t < N_GRAPHS) atomicAdd(&g_cnt[t], scnt[t]);
}

// ---------------- final: out[g][o] = (pool[g]/cnt[g] + b2) @ Wfc + bfc ----------------
__global__ void k_final(const float* __restrict__ b2, const float* __restrict__ Wfc,
                        const float* __restrict__ bfc, float* __restrict__ out) {
    __shared__ float P[N_GRAPHS][HID];
    for (int i = threadIdx.x; i < N_GRAPHS * HID; i += 128) {
        int g = i / HID, c = i % HID;
        float cnt = fmaxf(g_cnt[g], 1.0f);
        P[g][c] = g_pool[i] / cnt + b2[c];
    }
    __syncthreads();
    int o = threadIdx.x;   // 128 threads
    for (int g = 0; g < N_GRAPHS; g++) {
        float s = bfc[o];
#pragma unroll
        for (int c = 0; c < HID; c++)
            s += P[g][c] * Wfc[c * OUT_DIM + o];
        out[g * OUT_DIM + o] = s;
    }
}

// ---------------- launcher ----------------
extern "C" void kernel_launch(void* const* d_in, const int* in_sizes, int n_in,
                              void* d_out, int out_size) {
    const float* x   = (const float*)d_in[0];
    const int*   ei  = (const int*)d_in[1];     // int64 inputs arrive as int32
    const float* ew  = (const float*)d_in[2];
    const int*   bat = (const int*)d_in[3];
    const float* W1  = (const float*)d_in[4];
    const float* b1  = (const float*)d_in[5];
    const float* W2  = (const float*)d_in[6];
    const float* b2  = (const float*)d_in[7];
    const float* Wfc = (const float*)d_in[8];
    const float* bfc = (const float*)d_in[9];
    float* out = (float*)d_out;

    int n = in_sizes[0] / IN_DIM;      // 100000
    int E = in_sizes[2];               // 3200000
    const int* src = ei;
    const int* dst = ei + E;

    float* bufB;
    __half* bufH;
    cudaGetSymbolAddress((void**)&bufB, g_bufB);
    cudaGetSymbolAddress((void**)&bufH, g_bufH);

    int gE4 = (E / 4 + 255) / 256;                // 3125 count/fill blocks
    int gN  = (n + 255) / 256;
    int GB  = (n + 127) / 128;                    // 782 gemm blocks
    int nsb = (n + 1023) / 1024;                  // 98 scan blocks

    // ---- init; count; scan; fused gemm1 || fill ----
    k_init0<<<gN, 256>>>(n);
    k_count<<<gE4, 256>>>(dst, ew, E);
    k_scan<<<nsb, 256>>>(n);
    k_gemm1_fill<<<GB + gE4, 256>>>(x, W1, bufH, src, dst, ew, n, E, GB);

    // ---- conv1 gather: agg1 -> bufB (fp32) ----
    k_gather_h<<<(n + 7) / 8, 256>>>(bufH, bufB, n);

    // ---- conv2: h2 = relu(agg1 + b1) @ W2 -> bufH (fp16) ; gather2+pool fused ----
    k_gemm2<<<GB, 256>>>(bufB, W2, b1, bufH, n);
    k_gather_pool<<<GP_BLOCKS, 256>>>(bufH, bat, n);

    // ---- final fc (b2 folded) ----
    k_final<<<1, 128>>>(b2, Wfc, bfc, out);
}